// round 9
// baseline (speedup 1.0000x reference)
#include <cuda_runtime.h>
#include <cuda_bf16.h>
#include <stdint.h>

// Problem constants (fixed by dataset)
#define DN 50000     // nodes
#define DE 600000    // edges
#define DD 128       // feature dim
#define DR 8         // relations
#define NR (DR * DN) // 400000 (rel,dst) segments, rel-major
#define NCHUNK 9     // 8 relations + root
#define FULLM 0xffffffffu
#define SB   131     // scan blocks (<= 148 SMs -> co-resident, spin-safe)
#define SPAN 3072    // elements per scan block (3 x 1024)

// ---------------- scratch (device globals; no allocs allowed) ----------------
// g_cnt and g_scan_flag must be zero at entry; zero-init covers the first call,
// tail_kernel re-zeroes them at the end of every launch sequence.
__device__ int   g_cnt[NR];              // per-(rel,dst) edge counts
__device__ int   g_rowptr2[NR + 1];      // CSR row pointers, rel-major (final)
__device__ int   g_woff[NR];             // working offsets for scatter
__device__ int   g_scan_agg[SB];
__device__ int   g_scan_pfx[SB];
__device__ int   g_scan_flag[SB];        // 0=none, 1=agg ready, 2=prefix ready
__device__ int2  g_emeta[DE];            // per-edge: .x = src | (dst<<16), .y = coef bits
__device__ float g_h[(size_t)DN * DD];   // layer-1 output
// weight tiles, tf32-rounded fp32, transposed layout [layer][chunk][n][k]
__device__ float g_wt[2 * NCHUNK * DD * DD];

__device__ __forceinline__ float to_tf32(float x) {
    float r;
    asm("cvt.rna.tf32.f32 %0, %1;" : "=f"(r) : "f"(x));
    return r;
}

// ---------------- preprocessing kernels ----------------
__global__ void count_kernel(const int* __restrict__ ei, const int* __restrict__ et, int E) {
    int e = blockIdx.x * blockDim.x + threadIdx.x;
    if (e < E) {
        int d = ei[E + e];
        int t = et[e];
        atomicAdd(&g_cnt[t * DN + d], 1);   // rel-major
    }
}

// single-pass scan with decoupled lookback (all SB blocks co-resident)
__global__ __launch_bounds__(1024) void scan_kernel(int E) {
    __shared__ int s[1024];
    __shared__ int sh_carry;
    __shared__ int sh_ex;
    const int tid = threadIdx.x;
    const int b   = blockIdx.x;
    if (tid == 0) sh_carry = 0;
    __syncthreads();
    const int base = b * SPAN;

    #pragma unroll
    for (int t = 0; t < 3; t++) {
        int i = base + t * 1024 + tid;
        int v = (i < NR) ? g_cnt[i] : 0;
        s[tid] = v;
        __syncthreads();
        for (int off = 1; off < 1024; off <<= 1) {
            int x = (tid >= off) ? s[tid - off] : 0;
            __syncthreads();
            s[tid] += x;
            __syncthreads();
        }
        int incl = s[tid];
        if (i < NR) g_rowptr2[i] = sh_carry + incl - v;   // block-local exclusive
        __syncthreads();
        if (tid == 1023) sh_carry += incl;
        __syncthreads();
    }
    int total = sh_carry;

    if (tid == 0) {
        g_scan_agg[b] = total;
        if (b == 0) { g_scan_pfx[0] = total; sh_ex = 0; }
        __threadfence();
        *(volatile int*)&g_scan_flag[b] = (b == 0) ? 2 : 1;
    }
    if (b > 0 && tid < 32) {
        int lane = tid;
        int ex = 0;
        int idx = b - 1;
        while (true) {
            int j = idx - lane;
            int f = 0;
            if (j >= 0) {
                do { f = *(volatile int*)&g_scan_flag[j]; } while (f == 0);
            }
            int v = 0;
            if (j >= 0)
                v = (f == 2) ? *(volatile int*)&g_scan_pfx[j]
                             : *(volatile int*)&g_scan_agg[j];
            unsigned m = __ballot_sync(FULLM, (j >= 0) && (f == 2));
            int lead = m ? (__ffs(m) - 1) : 32;
            int contrib = (j >= 0 && lane <= lead) ? v : 0;
            #pragma unroll
            for (int off = 16; off; off >>= 1)
                contrib += __shfl_down_sync(FULLM, contrib, off);
            contrib = __shfl_sync(FULLM, contrib, 0);
            ex += contrib;
            if (m) break;
            idx -= 32;
        }
        if (lane == 0) {
            sh_ex = ex;
            g_scan_pfx[b] = ex + total;
            __threadfence();
            *(volatile int*)&g_scan_flag[b] = 2;
        }
    }
    __syncthreads();
    int ex = sh_ex;
    #pragma unroll
    for (int t = 0; t < 3; t++) {
        int i = base + t * 1024 + tid;
        if (i < NR) {
            int val = g_rowptr2[i] + ex;
            g_rowptr2[i] = val;
            g_woff[i] = val;
        }
    }
    if (b == 0 && tid == 0) g_rowptr2[NR] = E;
}

// merged: scatter (blocks [0,EB)) + weight prep (blocks [EB, EB+WB))
__global__ void scatter_wprep_kernel(
    const int* __restrict__ ei, const int* __restrict__ et, int E, int EB,
    const float* __restrict__ W1, const float* __restrict__ r1,
    const float* __restrict__ W2, const float* __restrict__ r2)
{
    int b = blockIdx.x;
    if (b < EB) {
        int e = b * 256 + threadIdx.x;
        if (e < E) {
            int s = ei[e];
            int d = ei[E + e];
            int t = et[e];
            int seg = t * DN + d;
            int pos = atomicAdd(&g_woff[seg], 1);
            int c = g_cnt[seg];
            float coef = 1.0f / (float)(c > 0 ? c : 1);
            g_emeta[pos] = make_int2((int)((unsigned)s | ((unsigned)d << 16)),
                                     __float_as_int(coef));
        }
    } else {
        int id = (b - EB) * 256 + threadIdx.x;
        const int total = 2 * NCHUNK * DD * DD;
        if (id < total) {
            int l   = id / (NCHUNK * DD * DD);
            int rem = id % (NCHUNK * DD * DD);
            int ch  = rem / (DD * DD);
            int pos = rem % (DD * DD);
            int n = pos >> 7, k = pos & 127;
            const float* W  = l ? W2 : W1;
            const float* rt = l ? r2 : r1;
            float wv = (ch < 8) ? W[((size_t)ch * DD + k) * DD + n] : rt[(size_t)k * DD + n];
            g_wt[id] = to_tf32(wv);
        }
    }
}

// tail: copy rel_emb to output AND re-zero g_cnt / scan flags for next replay
__global__ void tail_kernel(const float* __restrict__ rel, float* __restrict__ out) {
    int i = blockIdx.x * blockDim.x + threadIdx.x;
    if (i < DR * DD) out[i] = rel[i];
    if (i < SB) g_scan_flag[i] = 0;
    for (int j = i; j < NR; j += gridDim.x * blockDim.x) g_cnt[j] = 0;
}

// ---------------- fused RGCN layer: warp-specialized, double-buffered ----------------
__device__ __forceinline__ void mma_tf32(float c[4],
    uint32_t a0, uint32_t a1, uint32_t a2, uint32_t a3,
    uint32_t b0, uint32_t b1)
{
    asm volatile(
        "mma.sync.aligned.m16n8k8.row.col.f32.tf32.tf32.f32 "
        "{%0,%1,%2,%3}, {%4,%5,%6,%7}, {%8,%9}, {%0,%1,%2,%3};\n"
        : "+f"(c[0]), "+f"(c[1]), "+f"(c[2]), "+f"(c[3])
        : "r"(a0), "r"(a1), "r"(a2), "r"(a3), "r"(b0), "r"(b1));
}

__device__ __forceinline__ void ldsm4(uint32_t& r0, uint32_t& r1, uint32_t& r2, uint32_t& r3,
                                      uint32_t addr)
{
    asm volatile("ldmatrix.sync.aligned.m8n8.x4.shared.b16 {%0,%1,%2,%3}, [%4];"
                 : "=r"(r0), "=r"(r1), "=r"(r2), "=r"(r3) : "r"(addr));
}

__device__ __forceinline__ void bar_sync(int id) {
    asm volatile("bar.sync %0, 256;" :: "r"(id) : "memory");
}
__device__ __forceinline__ void bar_arrive(int id) {
    asm volatile("bar.arrive %0, 256;" :: "r"(id) : "memory");
}

#define MT    64   // M tile (nodes per CTA)
#define PAD   132  // fp32 row stride (conflict-free frag loads)
#define A_FLOATS (MT * PAD)
#define B_FLOATS (128 * PAD)
#define SMEM_BYTES ((2 * A_FLOATS + 2 * B_FLOATS) * 4)   // 202,752 B

// barrier ids: EMPTY[buf] = 1+buf, FULL[buf] = 3+buf
__global__ __launch_bounds__(256, 1) void fused_layer_kernel(
    const float* __restrict__ X,
    const float* __restrict__ WT,    // layer base of g_wt
    const float* __restrict__ bias,
    float* __restrict__ out, int N)
{
    extern __shared__ char smem[];
    float* As = (float*)smem;               // 2 x (MT x PAD)
    float* Bs = As + 2 * A_FLOATS;          // 2 x (128 x PAD)

    const int tid  = threadIdx.x;
    const int w    = tid >> 5;              // 0..7
    const int lane = tid & 31;
    const int m0   = blockIdx.x * MT;

    if (w < 4) {
        // ================= PRODUCER (warps 0-3): gather A, load B =================
        const int w16 = w * 16;             // this warp's 16 contiguous A rows
        for (int ch = 0; ch < NCHUNK; ch++) {
            const int buf = ch & 1;
            bar_sync(1 + buf);              // wait buffer empty

            float* Ab = As + buf * A_FLOATS;
            float* Bb = Bs + buf * B_FLOATS;

            // ---- B tile via cp.async.ca ----
            {
                const float* src = WT + ch * (DD * DD);
                #pragma unroll
                for (int v = 0; v < 32; v++) {
                    int flat = v * 128 + tid;      // 4096 chunks of 4 floats
                    int n  = flat >> 5;
                    int kc = (flat & 31) << 2;
                    uint32_t daddr = (uint32_t)__cvta_generic_to_shared(Bb + n * PAD + kc);
                    asm volatile("cp.async.ca.shared.global [%0], [%1], 16;\n"
                                 :: "r"(daddr), "l"(src + n * DD + kc));
                }
                asm volatile("cp.async.commit_group;\n");
            }

            // ---- build A tile (fp32) ----
            if (ch < 8) {
                #pragma unroll
                for (int i = 0; i < 16; i++)
                    *(float4*)(Ab + (w16 + i) * PAD + lane * 4) =
                        make_float4(0.f, 0.f, 0.f, 0.f);

                int r0c = m0 + w16;      if (r0c > N) r0c = N;
                int r1c = m0 + w16 + 16; if (r1c > N) r1c = N;
                int wbeg = g_rowptr2[ch * DN + r0c];
                int wend = g_rowptr2[ch * DN + r1c];

                for (int e0 = wbeg; e0 < wend; e0 += 32) {
                    int idx = e0 + lane;
                    int2 mt = make_int2(0, 0);
                    if (idx < wend) mt = g_emeta[idx];
                    int cnt = wend - e0; if (cnt > 32) cnt = 32;
                    for (int j = 0; j < cnt; j += 8) {
                        int nb = cnt - j; if (nb > 8) nb = 8;
                        int pk[8]; float cc[8]; float4 v[8];
                        #pragma unroll
                        for (int q = 0; q < 8; q++) {
                            pk[q] = __shfl_sync(FULLM, mt.x, j + q);
                            cc[q] = __shfl_sync(FULLM, __int_as_float(mt.y), j + q);
                        }
                        #pragma unroll
                        for (int q = 0; q < 8; q++)
                            if (q < nb)
                                v[q] = *(const float4*)(X +
                                       (size_t)((unsigned)pk[q] & 0xffffu) * DD + lane * 4);
                        #pragma unroll
                        for (int q = 0; q < 8; q++)
                            if (q < nb) {
                                int dl = (int)(((unsigned)pk[q]) >> 16) - m0;
                                float* rp = Ab + dl * PAD + lane * 4;
                                float4 cur = *(float4*)rp;
                                cur.x += cc[q] * v[q].x;
                                cur.y += cc[q] * v[q].y;
                                cur.z += cc[q] * v[q].z;
                                cur.w += cc[q] * v[q].w;
                                *(float4*)rp = cur;
                            }
                    }
                }
                #pragma unroll
                for (int i = 0; i < 16; i++) {
                    float* rp = Ab + (w16 + i) * PAD + lane * 4;
                    float4 vv = *(float4*)rp;
                    vv.x = to_tf32(vv.x); vv.y = to_tf32(vv.y);
                    vv.z = to_tf32(vv.z); vv.w = to_tf32(vv.w);
                    *(float4*)rp = vv;
                }
            } else {
                // root chunk: A = X tile (tf32-rounded)
                #pragma unroll
                for (int i = 0; i < 16; i++) {
                    int row  = w16 + i;
                    int node = m0 + row;
                    float4 v = make_float4(0.f, 0.f, 0.f, 0.f);
                    if (node < N) v = *(const float4*)(X + (size_t)node * DD + lane * 4);
                    v.x = to_tf32(v.x); v.y = to_tf32(v.y);
                    v.z = to_tf32(v.z); v.w = to_tf32(v.w);
                    *(float4*)(Ab + row * PAD + lane * 4) = v;
                }
            }
            asm volatile("cp.async.wait_group 0;\n" ::: "memory");
            bar_arrive(3 + buf);            // buffer full
        }
    } else {
        // ================= CONSUMER (warps 4-7): ldmatrix + MMA =================
        const int cw = w - 4;               // 0..3: rows cw*16 .. cw*16+15
        const int g = lane >> 2;
        const int t = lane & 3;

        float C[16][4];
        #pragma unroll
        for (int nf = 0; nf < 16; nf++)
            #pragma unroll
            for (int q = 0; q < 4; q++) C[nf][q] = 0.0f;

        uint32_t As_u = (uint32_t)__cvta_generic_to_shared(As);
        uint32_t Bs_u = (uint32_t)__cvta_generic_to_shared(Bs);
        uint32_t a_addr = As_u + (((cw * 16 + (lane & 15)) * PAD) + ((lane >> 4) << 2)) * 4;
        uint32_t b_addr[8];
        #pragma unroll
        for (int j = 0; j < 8; j++) {
            int n0 = j * 16;
            b_addr[j] = Bs_u + (((n0 + (lane & 7) + ((lane & 16) >> 1)) * PAD)
                                + ((lane & 8) >> 1)) * 4;
        }

        // buffers start empty: permit the first two producer fills
        bar_arrive(1);
        bar_arrive(2);

        for (int ch = 0; ch < NCHUNK; ch++) {
            const int buf = ch & 1;
            bar_sync(3 + buf);              // wait buffer full
            uint32_t aoff = buf * (A_FLOATS * 4);
            uint32_t boff = buf * (B_FLOATS * 4);

            #pragma unroll
            for (int ks = 0; ks < 16; ks++) {
                uint32_t koff = ks * 32;     // 8 floats * 4B
                uint32_t bf[16][2];
                #pragma unroll
                for (int j = 0; j < 8; j++)
                    ldsm4(bf[2*j][0], bf[2*j][1], bf[2*j+1][0], bf[2*j+1][1],
                          b_addr[j] + boff + koff);
                uint32_t af[4];
                ldsm4(af[0], af[1], af[2], af[3], a_addr + aoff + koff);
                #pragma unroll
                for (int nf = 0; nf < 16; nf++)
                    mma_tf32(C[nf], af[0], af[1], af[2], af[3],
                             bf[nf][0], bf[nf][1]);
            }
            bar_arrive(1 + buf);            // buffer empty
        }

        // ---- epilogue: + bias, ReLU ----
        #pragma unroll
        for (int nf = 0; nf < 16; nf++) {
            int col = nf * 8 + 2 * t;
            float b0 = bias[col], b1 = bias[col + 1];
            int row = cw * 16 + g;
            int node0 = m0 + row;
            if (node0 < N) {
                float o0 = C[nf][0] + b0; o0 = o0 > 0.f ? o0 : 0.f;
                float o1 = C[nf][1] + b1; o1 = o1 > 0.f ? o1 : 0.f;
                *(float2*)(out + (size_t)node0 * DD + col) = make_float2(o0, o1);
            }
            int node1 = node0 + 8;
            if (node1 < N && row + 8 < MT + 16) {
                float o2 = C[nf][2] + b0; o2 = o2 > 0.f ? o2 : 0.f;
                float o3 = C[nf][3] + b1; o3 = o3 > 0.f ? o3 : 0.f;
                *(float2*)(out + (size_t)node1 * DD + col) = make_float2(o2, o3);
            }
        }
    }
}

// ---------------- launch ----------------
extern "C" void kernel_launch(void* const* d_in, const int* in_sizes, int n_in,
                              void* d_out, int out_size) {
    const float* x     = (const float*)d_in[0];
    const int*   ei    = (const int*)d_in[1];
    const int*   et    = (const int*)d_in[2];
    const float* W1    = (const float*)d_in[3];
    const float* root1 = (const float*)d_in[4];
    const float* b1    = (const float*)d_in[5];
    const float* W2    = (const float*)d_in[6];
    const float* root2 = (const float*)d_in[7];
    const float* b2    = (const float*)d_in[8];
    const float* rel   = (const float*)d_in[9];

    const int N = in_sizes[0] / DD;   // 50000
    const int E = in_sizes[2];        // 600000

    float* h1;  cudaGetSymbolAddress((void**)&h1, g_h);
    float* wt;  cudaGetSymbolAddress((void**)&wt, g_wt);

    float* out_h   = (float*)d_out;
    float* out_rel = (float*)d_out + (size_t)N * DD;

    static int smem_set = 0;
    if (!smem_set) {
        cudaFuncSetAttribute(fused_layer_kernel,
                             cudaFuncAttributeMaxDynamicSharedMemorySize, SMEM_BYTES);
        smem_set = 1;
    }

    // ---- preprocessing: 3 launches ----
    count_kernel<<<(E + 255) / 256, 256>>>(ei, et, E);             // launch 1
    scan_kernel<<<SB, 1024>>>(E);                                  // launch 2
    const int EB = (E + 255) / 256;
    const int WB = (2 * NCHUNK * DD * DD + 255) / 256;
    scatter_wprep_kernel<<<EB + WB, 256>>>(ei, et, E, EB,
                                           W1, root1, W2, root2);  // launch 3

    const int grid = (N + MT - 1) / MT;   // 782

    // ---- layer 1 (launch 4 — ncu capture lands here) ----
    fused_layer_kernel<<<grid, 256, SMEM_BYTES>>>(x, wt, b1, h1, N);
    // ---- layer 2 ----
    fused_layer_kernel<<<grid, 256, SMEM_BYTES>>>(h1, wt + NCHUNK * DD * DD, b2, out_h, N);

    // ---- tail: rel_emb copy + re-zero for next replay ----
    tail_kernel<<<400, 1024>>>(rel, out_rel);
}

// round 10
// speedup vs baseline: 1.2043x; 1.2043x over previous
#include <cuda_runtime.h>
#include <cuda_bf16.h>
#include <stdint.h>

// Problem constants (fixed by dataset)
#define DN 50000     // nodes
#define DE 600000    // edges
#define DD 128       // feature dim
#define DR 8         // relations
#define NR (DR * DN) // 400000 (rel,dst) segments, rel-major
#define NCHUNK 9     // root + 8 relations
#define FULLM 0xffffffffu
#define SB   131     // scan blocks (<= 148 SMs -> co-resident, spin-safe)
#define SPAN 3072    // elements per scan block (3 x 1024)

// ---------------- scratch (device globals; no allocs allowed) ----------------
// g_cnt and g_scan_flag must be zero at entry; zero-init covers the first call,
// tail_kernel re-zeroes them at the end of every launch sequence.
__device__ int   g_cnt[NR];              // per-(rel,dst) edge counts
__device__ int   g_rowptr2[NR + 1];      // CSR row pointers, rel-major (final)
__device__ int   g_woff[NR];             // working offsets for scatter
__device__ int   g_scan_agg[SB];
__device__ int   g_scan_pfx[SB];
__device__ int   g_scan_flag[SB];        // 0=none, 1=agg ready, 2=prefix ready
__device__ int2  g_emeta[DE];            // per-edge: .x = src | (dst<<16), .y = coef bits
__device__ float g_h[(size_t)DN * DD];   // layer-1 output
// weight tiles, tf32-rounded fp32, transposed layout [layer][chunk][n][k]
// chunk order: 0 = root, 1..8 = relations 0..7
__device__ float g_wt[2 * NCHUNK * DD * DD];

__device__ __forceinline__ float to_tf32(float x) {
    float r;
    asm("cvt.rna.tf32.f32 %0, %1;" : "=f"(r) : "f"(x));
    return r;
}

// ---------------- preprocessing kernels ----------------
__global__ void count_kernel(const int* __restrict__ ei, const int* __restrict__ et, int E) {
    int e = blockIdx.x * blockDim.x + threadIdx.x;
    if (e < E) {
        int d = ei[E + e];
        int t = et[e];
        atomicAdd(&g_cnt[t * DN + d], 1);   // rel-major
    }
}

// single-pass scan with decoupled lookback (all SB blocks co-resident)
__global__ __launch_bounds__(1024) void scan_kernel(int E) {
    __shared__ int s[1024];
    __shared__ int sh_carry;
    __shared__ int sh_ex;
    const int tid = threadIdx.x;
    const int b   = blockIdx.x;
    if (tid == 0) sh_carry = 0;
    __syncthreads();
    const int base = b * SPAN;

    #pragma unroll
    for (int t = 0; t < 3; t++) {
        int i = base + t * 1024 + tid;
        int v = (i < NR) ? g_cnt[i] : 0;
        s[tid] = v;
        __syncthreads();
        for (int off = 1; off < 1024; off <<= 1) {
            int x = (tid >= off) ? s[tid - off] : 0;
            __syncthreads();
            s[tid] += x;
            __syncthreads();
        }
        int incl = s[tid];
        if (i < NR) g_rowptr2[i] = sh_carry + incl - v;   // block-local exclusive
        __syncthreads();
        if (tid == 1023) sh_carry += incl;
        __syncthreads();
    }
    int total = sh_carry;

    if (tid == 0) {
        g_scan_agg[b] = total;
        if (b == 0) { g_scan_pfx[0] = total; sh_ex = 0; }
        __threadfence();
        *(volatile int*)&g_scan_flag[b] = (b == 0) ? 2 : 1;
    }
    if (b > 0 && tid < 32) {
        int lane = tid;
        int ex = 0;
        int idx = b - 1;
        while (true) {
            int j = idx - lane;
            int f = 0;
            if (j >= 0) {
                do { f = *(volatile int*)&g_scan_flag[j]; } while (f == 0);
            }
            int v = 0;
            if (j >= 0)
                v = (f == 2) ? *(volatile int*)&g_scan_pfx[j]
                             : *(volatile int*)&g_scan_agg[j];
            unsigned m = __ballot_sync(FULLM, (j >= 0) && (f == 2));
            int lead = m ? (__ffs(m) - 1) : 32;
            int contrib = (j >= 0 && lane <= lead) ? v : 0;
            #pragma unroll
            for (int off = 16; off; off >>= 1)
                contrib += __shfl_down_sync(FULLM, contrib, off);
            contrib = __shfl_sync(FULLM, contrib, 0);
            ex += contrib;
            if (m) break;
            idx -= 32;
        }
        if (lane == 0) {
            sh_ex = ex;
            g_scan_pfx[b] = ex + total;
            __threadfence();
            *(volatile int*)&g_scan_flag[b] = 2;
        }
    }
    __syncthreads();
    int ex = sh_ex;
    #pragma unroll
    for (int t = 0; t < 3; t++) {
        int i = base + t * 1024 + tid;
        if (i < NR) {
            int val = g_rowptr2[i] + ex;
            g_rowptr2[i] = val;
            g_woff[i] = val;
        }
    }
    if (b == 0 && tid == 0) g_rowptr2[NR] = E;
}

// merged: scatter (blocks [0,EB)) + weight prep (blocks [EB, EB+WB))
__global__ void scatter_wprep_kernel(
    const int* __restrict__ ei, const int* __restrict__ et, int E, int EB,
    const float* __restrict__ W1, const float* __restrict__ r1,
    const float* __restrict__ W2, const float* __restrict__ r2)
{
    int b = blockIdx.x;
    if (b < EB) {
        int e = b * 256 + threadIdx.x;
        if (e < E) {
            int s = ei[e];
            int d = ei[E + e];
            int t = et[e];
            int seg = t * DN + d;
            int pos = atomicAdd(&g_woff[seg], 1);
            int c = g_cnt[seg];
            float coef = 1.0f / (float)(c > 0 ? c : 1);
            g_emeta[pos] = make_int2((int)((unsigned)s | ((unsigned)d << 16)),
                                     __float_as_int(coef));
        }
    } else {
        int id = (b - EB) * 256 + threadIdx.x;
        const int total = 2 * NCHUNK * DD * DD;
        if (id < total) {
            int l   = id / (NCHUNK * DD * DD);
            int rem = id % (NCHUNK * DD * DD);
            int ch  = rem / (DD * DD);      // 0 = root, 1..8 = relations 0..7
            int pos = rem % (DD * DD);
            int n = pos >> 7, k = pos & 127;
            const float* W  = l ? W2 : W1;
            const float* rt = l ? r2 : r1;
            float wv = (ch > 0) ? W[((size_t)(ch - 1) * DD + k) * DD + n]
                                : rt[(size_t)k * DD + n];
            g_wt[id] = to_tf32(wv);
        }
    }
}

// tail: copy rel_emb to output AND re-zero g_cnt / scan flags for next replay
__global__ void tail_kernel(const float* __restrict__ rel, float* __restrict__ out) {
    int i = blockIdx.x * blockDim.x + threadIdx.x;
    if (i < DR * DD) out[i] = rel[i];
    if (i < SB) g_scan_flag[i] = 0;
    for (int j = i; j < NR; j += gridDim.x * blockDim.x) g_cnt[j] = 0;
}

// ---------------- fused RGCN layer (MT=128, B double-buffered cp.async) ----------
__device__ __forceinline__ void mma_tf32(float c[4],
    uint32_t a0, uint32_t a1, uint32_t a2, uint32_t a3,
    uint32_t b0, uint32_t b1)
{
    asm volatile(
        "mma.sync.aligned.m16n8k8.row.col.f32.tf32.tf32.f32 "
        "{%0,%1,%2,%3}, {%4,%5,%6,%7}, {%8,%9}, {%0,%1,%2,%3};\n"
        : "+f"(c[0]), "+f"(c[1]), "+f"(c[2]), "+f"(c[3])
        : "r"(a0), "r"(a1), "r"(a2), "r"(a3), "r"(b0), "r"(b1));
}

__device__ __forceinline__ void ldsm4(uint32_t& r0, uint32_t& r1, uint32_t& r2, uint32_t& r3,
                                      uint32_t addr)
{
    asm volatile("ldmatrix.sync.aligned.m8n8.x4.shared.b16 {%0,%1,%2,%3}, [%4];"
                 : "=r"(r0), "=r"(r1), "=r"(r2), "=r"(r3) : "r"(addr));
}

#define MT    128  // M tile (nodes per CTA)
#define PAD   132  // fp32 row stride (conflict-free frag loads)
#define A_FLOATS (MT * PAD)
#define B_FLOATS (128 * PAD)
#define SMEM_BYTES ((A_FLOATS + 2 * B_FLOATS) * 4)   // 202,752 B

__global__ __launch_bounds__(256, 1) void fused_layer_kernel(
    const float* __restrict__ X,
    const float* __restrict__ WT,    // layer base of g_wt (chunk 0 = root)
    const float* __restrict__ bias,
    float* __restrict__ out, int N)
{
    extern __shared__ char smem[];
    float* As = (float*)smem;               // MT x PAD
    float* Bs = As + A_FLOATS;              // 2 x (128 x PAD)

    const int tid  = threadIdx.x;
    const int w    = tid >> 5;              // 0..7
    const int lane = tid & 31;
    const int m0   = blockIdx.x * MT;
    const int warp_m = w >> 1;              // 0..3 (32 rows each)
    const int warp_n = w & 1;               // 0..1 (64 cols each)
    const int g = lane >> 2;
    const int t = lane & 3;
    const int w16 = w * 16;                 // this warp's 16 contiguous A rows

    float C[2][8][4];
    #pragma unroll
    for (int a = 0; a < 2; a++)
        #pragma unroll
        for (int b = 0; b < 8; b++)
            #pragma unroll
            for (int q = 0; q < 4; q++) C[a][b][q] = 0.0f;

    // ldmatrix lane addresses (shared-space, bytes)
    uint32_t As_u = (uint32_t)__cvta_generic_to_shared(As);
    uint32_t Bs_u = (uint32_t)__cvta_generic_to_shared(Bs);
    uint32_t a_addr[2];
    #pragma unroll
    for (int mf = 0; mf < 2; mf++) {
        int r0m = warp_m * 32 + mf * 16;
        a_addr[mf] = As_u + (((r0m + (lane & 15)) * PAD) + ((lane >> 4) << 2)) * 4;
    }
    uint32_t b_addr[4];
    #pragma unroll
    for (int j = 0; j < 4; j++) {
        int n0 = warp_n * 64 + j * 16;
        b_addr[j] = Bs_u + (((n0 + (lane & 7) + ((lane & 16) >> 1)) * PAD)
                            + ((lane & 8) >> 1)) * 4;
    }

    // ---- prefetch B[0] ----
    {
        const float* src = WT;
        #pragma unroll
        for (int v = 0; v < 16; v++) {
            int flat = v * 256 + tid;
            int n  = flat >> 5;
            int kc = (flat & 31) << 2;
            uint32_t daddr = (uint32_t)__cvta_generic_to_shared(Bs + n * PAD + kc);
            asm volatile("cp.async.cg.shared.global [%0], [%1], 16;\n"
                         :: "r"(daddr), "l"(src + n * DD + kc));
        }
        asm volatile("cp.async.commit_group;\n");
    }

    for (int ch = 0; ch < NCHUNK; ch++) {
        const int buf = ch & 1;

        // ---- prefetch B[ch+1] into other buffer ----
        if (ch + 1 < NCHUNK) {
            const float* src = WT + (ch + 1) * (DD * DD);
            float* Bb = Bs + (1 - buf) * B_FLOATS;
            #pragma unroll
            for (int v = 0; v < 16; v++) {
                int flat = v * 256 + tid;
                int n  = flat >> 5;
                int kc = (flat & 31) << 2;
                uint32_t daddr = (uint32_t)__cvta_generic_to_shared(Bb + n * PAD + kc);
                asm volatile("cp.async.cg.shared.global [%0], [%1], 16;\n"
                             :: "r"(daddr), "l"(src + n * DD + kc));
            }
            asm volatile("cp.async.commit_group;\n");
        }

        // ---- build A tile (fp32) ----
        if (ch > 0) {
            int rel = ch - 1;
            #pragma unroll
            for (int i = 0; i < 16; i++)
                *(float4*)(As + (w16 + i) * PAD + lane * 4) =
                    make_float4(0.f, 0.f, 0.f, 0.f);

            int r0c = m0 + w16;      if (r0c > N) r0c = N;
            int r1c = m0 + w16 + 16; if (r1c > N) r1c = N;
            int wbeg = g_rowptr2[rel * DN + r0c];
            int wend = g_rowptr2[rel * DN + r1c];

            for (int e0 = wbeg; e0 < wend; e0 += 32) {
                int idx = e0 + lane;
                int2 mt = make_int2(0, 0);
                if (idx < wend) mt = g_emeta[idx];
                int cnt = wend - e0; if (cnt > 32) cnt = 32;
                for (int j = 0; j < cnt; j += 8) {
                    int nb = cnt - j; if (nb > 8) nb = 8;
                    int pk[8]; float cc[8]; float4 v[8];
                    #pragma unroll
                    for (int q = 0; q < 8; q++) {
                        pk[q] = __shfl_sync(FULLM, mt.x, j + q);
                        cc[q] = __shfl_sync(FULLM, __int_as_float(mt.y), j + q);
                    }
                    #pragma unroll
                    for (int q = 0; q < 8; q++)
                        if (q < nb)
                            v[q] = *(const float4*)(X +
                                   (size_t)((unsigned)pk[q] & 0xffffu) * DD + lane * 4);
                    #pragma unroll
                    for (int q = 0; q < 8; q++)
                        if (q < nb) {
                            int dl = (int)(((unsigned)pk[q]) >> 16) - m0;
                            float* rp = As + dl * PAD + lane * 4;
                            float4 cur = *(float4*)rp;
                            cur.x += cc[q] * v[q].x;
                            cur.y += cc[q] * v[q].y;
                            cur.z += cc[q] * v[q].z;
                            cur.w += cc[q] * v[q].w;
                            *(float4*)rp = cur;
                        }
                }
            }
            // tf32-round this warp's rows in place
            #pragma unroll
            for (int i = 0; i < 16; i++) {
                float* rp = As + (w16 + i) * PAD + lane * 4;
                float4 vv = *(float4*)rp;
                vv.x = to_tf32(vv.x); vv.y = to_tf32(vv.y);
                vv.z = to_tf32(vv.z); vv.w = to_tf32(vv.w);
                *(float4*)rp = vv;
            }
        } else {
            // root chunk: A = X tile (tf32-rounded)
            #pragma unroll
            for (int i = 0; i < 16; i++) {
                int row  = w16 + i;
                int node = m0 + row;
                float4 v = make_float4(0.f, 0.f, 0.f, 0.f);
                if (node < N) v = *(const float4*)(X + (size_t)node * DD + lane * 4);
                v.x = to_tf32(v.x); v.y = to_tf32(v.y);
                v.z = to_tf32(v.z); v.w = to_tf32(v.w);
                *(float4*)(As + row * PAD + lane * 4) = v;
            }
        }

        // wait for B[ch]; allow B[ch+1] to keep flying
        if (ch + 1 < NCHUNK)
            asm volatile("cp.async.wait_group 1;\n" ::: "memory");
        else
            asm volatile("cp.async.wait_group 0;\n" ::: "memory");
        __syncthreads();

        // ---- MMA: 16 k-steps of m16n8k8 tf32 ----
        uint32_t boff = buf * (B_FLOATS * 4);
        #pragma unroll
        for (int ks = 0; ks < 16; ks++) {
            uint32_t koff = ks * 32;
            uint32_t bf[8][2];
            #pragma unroll
            for (int j = 0; j < 4; j++)
                ldsm4(bf[2*j][0], bf[2*j][1], bf[2*j+1][0], bf[2*j+1][1],
                      b_addr[j] + boff + koff);
            uint32_t af[2][4];
            #pragma unroll
            for (int mf = 0; mf < 2; mf++)
                ldsm4(af[mf][0], af[mf][1], af[mf][2], af[mf][3],
                      a_addr[mf] + koff);
            #pragma unroll
            for (int mf = 0; mf < 2; mf++)
                #pragma unroll
                for (int nf = 0; nf < 8; nf++)
                    mma_tf32(C[mf][nf], af[mf][0], af[mf][1], af[mf][2], af[mf][3],
                             bf[nf][0], bf[nf][1]);
        }
        __syncthreads();   // A frag reads done before next chunk's gather rewrites A
    }

    // ---- epilogue: + bias, ReLU ----
    #pragma unroll
    for (int mf = 0; mf < 2; mf++)
        #pragma unroll
        for (int nf = 0; nf < 8; nf++) {
            int row = warp_m * 32 + mf * 16 + g;
            int col = warp_n * 64 + nf * 8 + 2 * t;
            float b0 = bias[col], b1 = bias[col + 1];
            int node0 = m0 + row;
            if (node0 < N) {
                float o0 = C[mf][nf][0] + b0; o0 = o0 > 0.f ? o0 : 0.f;
                float o1 = C[mf][nf][1] + b1; o1 = o1 > 0.f ? o1 : 0.f;
                *(float2*)(out + (size_t)node0 * DD + col) = make_float2(o0, o1);
            }
            int node1 = m0 + row + 8;
            if (node1 < N) {
                float o2 = C[mf][nf][2] + b0; o2 = o2 > 0.f ? o2 : 0.f;
                float o3 = C[mf][nf][3] + b1; o3 = o3 > 0.f ? o3 : 0.f;
                *(float2*)(out + (size_t)node1 * DD + col) = make_float2(o2, o3);
            }
        }
}

// ---------------- launch ----------------
extern "C" void kernel_launch(void* const* d_in, const int* in_sizes, int n_in,
                              void* d_out, int out_size) {
    const float* x     = (const float*)d_in[0];
    const int*   ei    = (const int*)d_in[1];
    const int*   et    = (const int*)d_in[2];
    const float* W1    = (const float*)d_in[3];
    const float* root1 = (const float*)d_in[4];
    const float* b1    = (const float*)d_in[5];
    const float* W2    = (const float*)d_in[6];
    const float* root2 = (const float*)d_in[7];
    const float* b2    = (const float*)d_in[8];
    const float* rel   = (const float*)d_in[9];

    const int N = in_sizes[0] / DD;   // 50000
    const int E = in_sizes[2];        // 600000

    float* h1;  cudaGetSymbolAddress((void**)&h1, g_h);
    float* wt;  cudaGetSymbolAddress((void**)&wt, g_wt);

    float* out_h   = (float*)d_out;
    float* out_rel = (float*)d_out + (size_t)N * DD;

    static int smem_set = 0;
    if (!smem_set) {
        cudaFuncSetAttribute(fused_layer_kernel,
                             cudaFuncAttributeMaxDynamicSharedMemorySize, SMEM_BYTES);
        smem_set = 1;
    }

    // ---- preprocessing: 3 launches ----
    count_kernel<<<(E + 255) / 256, 256>>>(ei, et, E);             // launch 1
    scan_kernel<<<SB, 1024>>>(E);                                  // launch 2
    const int EB = (E + 255) / 256;
    const int WB = (2 * NCHUNK * DD * DD + 255) / 256;
    scatter_wprep_kernel<<<EB + WB, 256>>>(ei, et, E, EB,
                                           W1, root1, W2, root2);  // launch 3

    const int grid = (N + MT - 1) / MT;   // 391

    // ---- layer 1 (launch 4 — ncu capture lands here) ----
    fused_layer_kernel<<<grid, 256, SMEM_BYTES>>>(x, wt, b1, h1, N);
    // ---- layer 2 ----
    fused_layer_kernel<<<grid, 256, SMEM_BYTES>>>(h1, wt + NCHUNK * DD * DD, b2, out_h, N);

    // ---- tail: rel_emb copy + re-zero for next replay ----
    tail_kernel<<<400, 1024>>>(rel, out_rel);
}

// round 11
// speedup vs baseline: 1.3188x; 1.0951x over previous
#include <cuda_runtime.h>
#include <cuda_bf16.h>
#include <stdint.h>

// Problem constants (fixed by dataset)
#define DN 50000     // nodes
#define DE 600000    // edges
#define DD 128       // feature dim
#define DR 8         // relations
#define NR (DR * DN) // 400000 (rel,dst) segments, rel-major
#define NCHUNK 9     // root + 8 relations
#define FULLM 0xffffffffu
#define SB   131     // scan blocks (<= 148 SMs -> co-resident, spin-safe)
#define SPAN 3072    // elements per scan block (3 x 1024)

// ---------------- scratch (device globals; no allocs allowed) ----------------
__device__ int   g_cnt[NR];              // per-(rel,dst) edge counts
__device__ int   g_rowptr2[NR + 1];      // CSR row pointers, rel-major (final)
__device__ int   g_woff[NR];             // working offsets for scatter
__device__ int   g_scan_agg[SB];
__device__ int   g_scan_pfx[SB];
__device__ int   g_scan_flag[SB];        // 0=none, 1=agg ready, 2=prefix ready
__device__ int2  g_emeta[DE];            // per-edge: .x = src | (dst<<16), .y = coef bits
__device__ float g_h[(size_t)DN * DD];   // layer-1 output
// weight tiles, tf32-rounded fp32, [layer][chunk][n][k], chunk 0 = root
__device__ float g_wt[2 * NCHUNK * DD * DD];

__device__ __forceinline__ float to_tf32(float x) {
    float r;
    asm("cvt.rna.tf32.f32 %0, %1;" : "=f"(r) : "f"(x));
    return r;
}

// ---------------- preprocessing kernels ----------------
__global__ void count_kernel(const int* __restrict__ ei, const int* __restrict__ et, int E) {
    int e = blockIdx.x * blockDim.x + threadIdx.x;
    if (e < E) {
        int d = ei[E + e];
        int t = et[e];
        atomicAdd(&g_cnt[t * DN + d], 1);   // rel-major
    }
}

// single-pass scan with decoupled lookback (all SB blocks co-resident)
__global__ __launch_bounds__(1024) void scan_kernel(int E) {
    __shared__ int s[1024];
    __shared__ int sh_carry;
    __shared__ int sh_ex;
    const int tid = threadIdx.x;
    const int b   = blockIdx.x;
    if (tid == 0) sh_carry = 0;
    __syncthreads();
    const int base = b * SPAN;

    #pragma unroll
    for (int t = 0; t < 3; t++) {
        int i = base + t * 1024 + tid;
        int v = (i < NR) ? g_cnt[i] : 0;
        s[tid] = v;
        __syncthreads();
        for (int off = 1; off < 1024; off <<= 1) {
            int x = (tid >= off) ? s[tid - off] : 0;
            __syncthreads();
            s[tid] += x;
            __syncthreads();
        }
        int incl = s[tid];
        if (i < NR) g_rowptr2[i] = sh_carry + incl - v;   // block-local exclusive
        __syncthreads();
        if (tid == 1023) sh_carry += incl;
        __syncthreads();
    }
    int total = sh_carry;

    if (tid == 0) {
        g_scan_agg[b] = total;
        if (b == 0) { g_scan_pfx[0] = total; sh_ex = 0; }
        __threadfence();
        *(volatile int*)&g_scan_flag[b] = (b == 0) ? 2 : 1;
    }
    if (b > 0 && tid < 32) {
        int lane = tid;
        int ex = 0;
        int idx = b - 1;
        while (true) {
            int j = idx - lane;
            int f = 0;
            if (j >= 0) {
                do { f = *(volatile int*)&g_scan_flag[j]; } while (f == 0);
            }
            int v = 0;
            if (j >= 0)
                v = (f == 2) ? *(volatile int*)&g_scan_pfx[j]
                             : *(volatile int*)&g_scan_agg[j];
            unsigned m = __ballot_sync(FULLM, (j >= 0) && (f == 2));
            int lead = m ? (__ffs(m) - 1) : 32;
            int contrib = (j >= 0 && lane <= lead) ? v : 0;
            #pragma unroll
            for (int off = 16; off; off >>= 1)
                contrib += __shfl_down_sync(FULLM, contrib, off);
            contrib = __shfl_sync(FULLM, contrib, 0);
            ex += contrib;
            if (m) break;
            idx -= 32;
        }
        if (lane == 0) {
            sh_ex = ex;
            g_scan_pfx[b] = ex + total;
            __threadfence();
            *(volatile int*)&g_scan_flag[b] = 2;
        }
    }
    __syncthreads();
    int ex = sh_ex;
    #pragma unroll
    for (int t = 0; t < 3; t++) {
        int i = base + t * 1024 + tid;
        if (i < NR) {
            int val = g_rowptr2[i] + ex;
            g_rowptr2[i] = val;
            g_woff[i] = val;
        }
    }
    if (b == 0 && tid == 0) g_rowptr2[NR] = E;
}

// merged: scatter (blocks [0,EB)) + weight prep (blocks [EB, EB+WB))
__global__ void scatter_wprep_kernel(
    const int* __restrict__ ei, const int* __restrict__ et, int E, int EB,
    const float* __restrict__ W1, const float* __restrict__ r1,
    const float* __restrict__ W2, const float* __restrict__ r2)
{
    int b = blockIdx.x;
    if (b < EB) {
        int e = b * 256 + threadIdx.x;
        if (e < E) {
            int s = ei[e];
            int d = ei[E + e];
            int t = et[e];
            int seg = t * DN + d;
            int pos = atomicAdd(&g_woff[seg], 1);
            int c = g_cnt[seg];
            float coef = 1.0f / (float)(c > 0 ? c : 1);
            g_emeta[pos] = make_int2((int)((unsigned)s | ((unsigned)d << 16)),
                                     __float_as_int(coef));
        }
    } else {
        int id = (b - EB) * 256 + threadIdx.x;
        const int total = 2 * NCHUNK * DD * DD;
        if (id < total) {
            int l   = id / (NCHUNK * DD * DD);
            int rem = id % (NCHUNK * DD * DD);
            int ch  = rem / (DD * DD);      // 0 = root, 1..8 = relations 0..7
            int pos = rem % (DD * DD);
            int n = pos >> 7, k = pos & 127;
            const float* W  = l ? W2 : W1;
            const float* rt = l ? r2 : r1;
            float wv = (ch > 0) ? W[((size_t)(ch - 1) * DD + k) * DD + n]
                                : rt[(size_t)k * DD + n];
            g_wt[id] = to_tf32(wv);
        }
    }
}

// tail: copy rel_emb to output AND re-zero g_cnt / scan flags for next replay
__global__ void tail_kernel(const float* __restrict__ rel, float* __restrict__ out) {
    int i = blockIdx.x * blockDim.x + threadIdx.x;
    if (i < DR * DD) out[i] = rel[i];
    if (i < SB) g_scan_flag[i] = 0;
    for (int j = i; j < NR; j += gridDim.x * blockDim.x) g_cnt[j] = 0;
}

// ---------------- fused RGCN layer (512 threads, MT=128, B double-buffered) ----
__device__ __forceinline__ void mma_tf32(float c[4],
    uint32_t a0, uint32_t a1, uint32_t a2, uint32_t a3,
    uint32_t b0, uint32_t b1)
{
    asm volatile(
        "mma.sync.aligned.m16n8k8.row.col.f32.tf32.tf32.f32 "
        "{%0,%1,%2,%3}, {%4,%5,%6,%7}, {%8,%9}, {%0,%1,%2,%3};\n"
        : "+f"(c[0]), "+f"(c[1]), "+f"(c[2]), "+f"(c[3])
        : "r"(a0), "r"(a1), "r"(a2), "r"(a3), "r"(b0), "r"(b1));
}

__device__ __forceinline__ void ldsm4(uint32_t& r0, uint32_t& r1, uint32_t& r2, uint32_t& r3,
                                      uint32_t addr)
{
    asm volatile("ldmatrix.sync.aligned.m8n8.x4.shared.b16 {%0,%1,%2,%3}, [%4];"
                 : "=r"(r0), "=r"(r1), "=r"(r2), "=r"(r3) : "r"(addr));
}

#define MT    128  // M tile (nodes per CTA)
#define NT    512  // threads per CTA (16 warps)
#define PAD   132  // fp32 row stride (conflict-free frag loads)
#define A_FLOATS (MT * PAD)
#define B_FLOATS (128 * PAD)
#define SMEM_BYTES ((A_FLOATS + 2 * B_FLOATS) * 4)   // 202,752 B

__global__ __launch_bounds__(NT, 1) void fused_layer_kernel(
    const float* __restrict__ X,
    const float* __restrict__ WT,    // layer base of g_wt (chunk 0 = root)
    const float* __restrict__ bias,
    float* __restrict__ out, int N)
{
    extern __shared__ char smem[];
    float* As = (float*)smem;               // MT x PAD
    float* Bs = As + A_FLOATS;              // 2 x (128 x PAD)

    const int tid  = threadIdx.x;
    const int w    = tid >> 5;              // 0..15
    const int lane = tid & 31;
    const int m0   = blockIdx.x * MT;
    const int warp_m = w >> 2;              // 0..3 (32 rows each)
    const int warp_n = w & 3;               // 0..3 (32 cols each)
    const int g = lane >> 2;
    const int t = lane & 3;
    const int w8 = w * 8;                   // this warp's 8 contiguous A rows

    float C[2][4][4];                       // 32 regs
    #pragma unroll
    for (int a = 0; a < 2; a++)
        #pragma unroll
        for (int b = 0; b < 4; b++)
            #pragma unroll
            for (int q = 0; q < 4; q++) C[a][b][q] = 0.0f;

    // ldmatrix lane addresses (shared-space, bytes)
    uint32_t As_u = (uint32_t)__cvta_generic_to_shared(As);
    uint32_t Bs_u = (uint32_t)__cvta_generic_to_shared(Bs);
    uint32_t a_addr[2];
    #pragma unroll
    for (int mf = 0; mf < 2; mf++) {
        int r0m = warp_m * 32 + mf * 16;
        a_addr[mf] = As_u + (((r0m + (lane & 15)) * PAD) + ((lane >> 4) << 2)) * 4;
    }
    uint32_t b_addr[2];
    #pragma unroll
    for (int j = 0; j < 2; j++) {
        int n0 = warp_n * 32 + j * 16;
        b_addr[j] = Bs_u + (((n0 + (lane & 7) + ((lane & 16) >> 1)) * PAD)
                            + ((lane & 8) >> 1)) * 4;
    }

    // ---- prefetch B[0] ----
    {
        const float* src = WT;
        #pragma unroll
        for (int v = 0; v < 8; v++) {
            int flat = v * NT + tid;         // 4096 chunks of 4 floats
            int n  = flat >> 5;
            int kc = (flat & 31) << 2;
            uint32_t daddr = (uint32_t)__cvta_generic_to_shared(Bs + n * PAD + kc);
            asm volatile("cp.async.cg.shared.global [%0], [%1], 16;\n"
                         :: "r"(daddr), "l"(src + n * DD + kc));
        }
        asm volatile("cp.async.commit_group;\n");
    }

    for (int ch = 0; ch < NCHUNK; ch++) {
        const int buf = ch & 1;

        // ---- prefetch B[ch+1] into other buffer ----
        if (ch + 1 < NCHUNK) {
            const float* src = WT + (ch + 1) * (DD * DD);
            float* Bb = Bs + (1 - buf) * B_FLOATS;
            #pragma unroll
            for (int v = 0; v < 8; v++) {
                int flat = v * NT + tid;
                int n  = flat >> 5;
                int kc = (flat & 31) << 2;
                uint32_t daddr = (uint32_t)__cvta_generic_to_shared(Bb + n * PAD + kc);
                asm volatile("cp.async.cg.shared.global [%0], [%1], 16;\n"
                             :: "r"(daddr), "l"(src + n * DD + kc));
            }
            asm volatile("cp.async.commit_group;\n");
        }

        // ---- build A tile (fp32); each warp owns 8 contiguous rows ----
        if (ch > 0) {
            int rel = ch - 1;
            #pragma unroll
            for (int i = 0; i < 8; i++)
                *(float4*)(As + (w8 + i) * PAD + lane * 4) =
                    make_float4(0.f, 0.f, 0.f, 0.f);

            int r0c = m0 + w8;      if (r0c > N) r0c = N;
            int r1c = m0 + w8 + 8;  if (r1c > N) r1c = N;
            int wbeg = g_rowptr2[rel * DN + r0c];
            int wend = g_rowptr2[rel * DN + r1c];

            for (int e0 = wbeg; e0 < wend; e0 += 32) {
                int idx = e0 + lane;
                int2 mt = make_int2(0, 0);
                if (idx < wend) mt = g_emeta[idx];
                int cnt = wend - e0; if (cnt > 32) cnt = 32;
                for (int j = 0; j < cnt; j += 8) {
                    int nb = cnt - j; if (nb > 8) nb = 8;
                    int pk[8]; float cc[8]; float4 v[8];
                    #pragma unroll
                    for (int q = 0; q < 8; q++) {
                        pk[q] = __shfl_sync(FULLM, mt.x, j + q);
                        cc[q] = __shfl_sync(FULLM, __int_as_float(mt.y), j + q);
                    }
                    #pragma unroll
                    for (int q = 0; q < 8; q++)
                        if (q < nb)
                            v[q] = *(const float4*)(X +
                                   (size_t)((unsigned)pk[q] & 0xffffu) * DD + lane * 4);
                    #pragma unroll
                    for (int q = 0; q < 8; q++)
                        if (q < nb) {
                            int dl = (int)(((unsigned)pk[q]) >> 16) - m0;
                            float* rp = As + dl * PAD + lane * 4;
                            float4 cur = *(float4*)rp;
                            cur.x += cc[q] * v[q].x;
                            cur.y += cc[q] * v[q].y;
                            cur.z += cc[q] * v[q].z;
                            cur.w += cc[q] * v[q].w;
                            *(float4*)rp = cur;
                        }
                }
            }
            // tf32-round this warp's rows in place
            #pragma unroll
            for (int i = 0; i < 8; i++) {
                float* rp = As + (w8 + i) * PAD + lane * 4;
                float4 vv = *(float4*)rp;
                vv.x = to_tf32(vv.x); vv.y = to_tf32(vv.y);
                vv.z = to_tf32(vv.z); vv.w = to_tf32(vv.w);
                *(float4*)rp = vv;
            }
        } else {
            // root chunk: A = X tile (tf32-rounded)
            #pragma unroll
            for (int i = 0; i < 8; i++) {
                int row  = w8 + i;
                int node = m0 + row;
                float4 v = make_float4(0.f, 0.f, 0.f, 0.f);
                if (node < N) v = *(const float4*)(X + (size_t)node * DD + lane * 4);
                v.x = to_tf32(v.x); v.y = to_tf32(v.y);
                v.z = to_tf32(v.z); v.w = to_tf32(v.w);
                *(float4*)(As + row * PAD + lane * 4) = v;
            }
        }

        // wait for B[ch]; allow B[ch+1] to keep flying
        if (ch + 1 < NCHUNK)
            asm volatile("cp.async.wait_group 1;\n" ::: "memory");
        else
            asm volatile("cp.async.wait_group 0;\n" ::: "memory");
        __syncthreads();

        // ---- MMA: 16 k-steps of m16n8k8 tf32; warp tile 32x32 ----
        uint32_t boff = buf * (B_FLOATS * 4);
        #pragma unroll
        for (int ks = 0; ks < 16; ks++) {
            uint32_t koff = ks * 32;
            uint32_t bf[4][2];
            #pragma unroll
            for (int j = 0; j < 2; j++)
                ldsm4(bf[2*j][0], bf[2*j][1], bf[2*j+1][0], bf[2*j+1][1],
                      b_addr[j] + boff + koff);
            uint32_t af[2][4];
            #pragma unroll
            for (int mf = 0; mf < 2; mf++)
                ldsm4(af[mf][0], af[mf][1], af[mf][2], af[mf][3],
                      a_addr[mf] + koff);
            #pragma unroll
            for (int mf = 0; mf < 2; mf++)
                #pragma unroll
                for (int nf = 0; nf < 4; nf++)
                    mma_tf32(C[mf][nf], af[mf][0], af[mf][1], af[mf][2], af[mf][3],
                             bf[nf][0], bf[nf][1]);
        }
        __syncthreads();   // A frag reads done before next chunk's gather rewrites A
    }

    // ---- epilogue: + bias, ReLU ----
    #pragma unroll
    for (int mf = 0; mf < 2; mf++)
        #pragma unroll
        for (int nf = 0; nf < 4; nf++) {
            int row = warp_m * 32 + mf * 16 + g;
            int col = warp_n * 32 + nf * 8 + 2 * t;
            float b0 = bias[col], b1 = bias[col + 1];
            int node0 = m0 + row;
            if (node0 < N) {
                float o0 = C[mf][nf][0] + b0; o0 = o0 > 0.f ? o0 : 0.f;
                float o1 = C[mf][nf][1] + b1; o1 = o1 > 0.f ? o1 : 0.f;
                *(float2*)(out + (size_t)node0 * DD + col) = make_float2(o0, o1);
            }
            int node1 = m0 + row + 8;
            if (node1 < N) {
                float o2 = C[mf][nf][2] + b0; o2 = o2 > 0.f ? o2 : 0.f;
                float o3 = C[mf][nf][3] + b1; o3 = o3 > 0.f ? o3 : 0.f;
                *(float2*)(out + (size_t)node1 * DD + col) = make_float2(o2, o3);
            }
        }
}

// ---------------- launch ----------------
extern "C" void kernel_launch(void* const* d_in, const int* in_sizes, int n_in,
                              void* d_out, int out_size) {
    const float* x     = (const float*)d_in[0];
    const int*   ei    = (const int*)d_in[1];
    const int*   et    = (const int*)d_in[2];
    const float* W1    = (const float*)d_in[3];
    const float* root1 = (const float*)d_in[4];
    const float* b1    = (const float*)d_in[5];
    const float* W2    = (const float*)d_in[6];
    const float* root2 = (const float*)d_in[7];
    const float* b2    = (const float*)d_in[8];
    const float* rel   = (const float*)d_in[9];

    const int N = in_sizes[0] / DD;   // 50000
    const int E = in_sizes[2];        // 600000

    float* h1;  cudaGetSymbolAddress((void**)&h1, g_h);
    float* wt;  cudaGetSymbolAddress((void**)&wt, g_wt);

    float* out_h   = (float*)d_out;
    float* out_rel = (float*)d_out + (size_t)N * DD;

    static int smem_set = 0;
    if (!smem_set) {
        cudaFuncSetAttribute(fused_layer_kernel,
                             cudaFuncAttributeMaxDynamicSharedMemorySize, SMEM_BYTES);
        smem_set = 1;
    }

    // ---- preprocessing: 3 launches ----
    count_kernel<<<(E + 255) / 256, 256>>>(ei, et, E);             // launch 1
    scan_kernel<<<SB, 1024>>>(E);                                  // launch 2
    const int EB = (E + 255) / 256;
    const int WB = (2 * NCHUNK * DD * DD + 255) / 256;
    scatter_wprep_kernel<<<EB + WB, 256>>>(ei, et, E, EB,
                                           W1, root1, W2, root2);  // launch 3

    const int grid = (N + MT - 1) / MT;   // 391

    // ---- layer 1 (launch 4 — ncu capture lands here) ----
    fused_layer_kernel<<<grid, NT, SMEM_BYTES>>>(x, wt, b1, h1, N);
    // ---- layer 2 ----
    fused_layer_kernel<<<grid, NT, SMEM_BYTES>>>(h1, wt + NCHUNK * DD * DD, b2, out_h, N);

    // ---- tail: rel_emb copy + re-zero for next replay ----
    tail_kernel<<<400, 1024>>>(rel, out_rel);
}